// round 15
// baseline (speedup 1.0000x reference)
#include <cuda_runtime.h>
#include <cuda_fp16.h>
#include <cstdint>

// R15: R13 base + (1) ga stride 264 (kills 4-way ACT_STORE bank conflict),
// (2) B-only x-partial hoist (no extra barrier), (3) XCONV moved off B's
// post-sync critical path. A group identical to R13.

#define CTAS  64
#define TPB   512
#define T_LEN 1024
#define GAS   264     // ga stride per batch-pair column (264 mod 32 = 8)

static __device__ float g_h2[512 * 64];

__device__ __forceinline__ uint32_t pkh(float a, float b) {
    __half ha = __float2half_rn(a), hb = __float2half_rn(b);
    return (uint32_t)__half_as_ushort(ha) | ((uint32_t)__half_as_ushort(hb) << 16);
}
__device__ __forceinline__ float tanhax(float x) {
    float y; asm("tanh.approx.f32 %0,%1;" : "=f"(y) : "f"(x)); return y;
}
__device__ __forceinline__ uint32_t cvt2h(float hi, float lo) {
    uint32_t r; asm("cvt.rn.f16x2.f32 %0,%1,%2;" : "=r"(r) : "f"(hi), "f"(lo)); return r;
}
__device__ __forceinline__ uint32_t tanh2(uint32_t v) {
    uint32_t r; asm("tanh.approx.f16x2 %0,%1;" : "=r"(r) : "r"(v)); return r;
}
__device__ __forceinline__ uint32_t tanh2_from(float lo, float hi) {
    return tanh2(cvt2h(hi, lo));
}
__device__ __forceinline__ uint32_t sig2_from(float lo, float hi) {
    uint32_t t = tanh2(cvt2h(0.5f * hi, 0.5f * lo));
    uint32_t r;
    asm("fma.rn.f16x2 %0,%1,%2,%3;" : "=r"(r)
        : "r"(t), "r"(0x38003800u), "r"(0x38003800u));
    return r;
}
__device__ __forceinline__ void mma16(float* d, const uint32_t* a, uint32_t b0, uint32_t b1) {
    asm volatile(
        "mma.sync.aligned.m16n8k16.row.col.f32.f16.f16.f32 "
        "{%0,%1,%2,%3},{%4,%5,%6,%7},{%8,%9},{%0,%1,%2,%3};"
        : "+f"(d[0]), "+f"(d[1]), "+f"(d[2]), "+f"(d[3])
        : "r"(a[0]), "r"(a[1]), "r"(a[2]), "r"(a[3]), "r"(b0), "r"(b1));
}
__device__ __forceinline__ void cpa16(uint32_t d, const void* s) {
    asm volatile("cp.async.ca.shared.global [%0],[%1],16;" :: "r"(d), "l"(s));
}
__device__ __forceinline__ void cpa4(uint32_t d, const void* s) {
    asm volatile("cp.async.ca.shared.global [%0],[%1],4;" :: "r"(d), "l"(s));
}
__device__ __forceinline__ uint32_t s2u(const void* p) {
    uint32_t a;
    asm("{.reg .u64 t; cvta.to.shared.u64 t,%1; cvt.u32.u64 %0,t;}" : "=r"(a) : "l"(p));
    return a;
}

__global__ void __launch_bounds__(TPB, 1)
lstm_kernel(const float* __restrict__ x,
            const float* __restrict__ w_ih1, const float* __restrict__ w_hh1,
            const float* __restrict__ b_ih1, const float* __restrict__ b_hh1,
            const float* __restrict__ w_ih2, const float* __restrict__ w_hh2,
            const float* __restrict__ b_ih2, const float* __restrict__ b_hh2) {
    __shared__ uint32_t h1d[2][256];
    __shared__ uint32_t h2v[256];
    __shared__ uint32_t xv[8][128];     // fp16-pair words [m*8+b]
    __shared__ float    xf[8][256];     // fp32 staging ring [b*32+k]
    __shared__ uint32_t ga2h[4 * GAS];
    __shared__ uint32_t ga1h[4 * GAS];

    const int tid = threadIdx.x;
    const int w   = tid >> 5, L = tid & 31;
    const int wg  = w & 7;
    const int gr  = L >> 2, q = L & 3;
    const int r1  = 32 * wg + gr, r2 = r1 + 8, r3 = r1 + 16, r4 = r1 + 24;
    const int bo  = 8 * q + gr;
    const bool isA = (w < 8);
    const bool tg  = ((wg >> 1) == 2);
    const int tl  = isA ? tid : tid - 256;
    const int uu  = tl & 63, j = tl >> 6;

    uint32_t WF[16][4];
    float bb1, bb2, bb3, bb4;
#define W2AT(r, k) ((k) < 64 ? w_ih2[(r) * 64 + (k)] : w_hh2[(r) * 64 + (k) - 64])
#define W1AT(r, k) ((k) < 64 ? w_hh1[(r) * 64 + (k)] : w_ih1[(r) * 32 + (k) - 64])
    if (isA) {
#pragma unroll
        for (int c = 0; c < 8; c++) {
            int k0 = 16 * c + 2 * q;
            WF[c][0] = pkh(W2AT(r1, k0),     W2AT(r1, k0 + 1));
            WF[c][1] = pkh(W2AT(r2, k0),     W2AT(r2, k0 + 1));
            WF[c][2] = pkh(W2AT(r1, k0 + 8), W2AT(r1, k0 + 9));
            WF[c][3] = pkh(W2AT(r2, k0 + 8), W2AT(r2, k0 + 9));
            WF[8 + c][0] = pkh(W2AT(r3, k0),     W2AT(r3, k0 + 1));
            WF[8 + c][1] = pkh(W2AT(r4, k0),     W2AT(r4, k0 + 1));
            WF[8 + c][2] = pkh(W2AT(r3, k0 + 8), W2AT(r3, k0 + 9));
            WF[8 + c][3] = pkh(W2AT(r4, k0 + 8), W2AT(r4, k0 + 9));
        }
        bb1 = b_ih2[r1] + b_hh2[r1]; bb2 = b_ih2[r2] + b_hh2[r2];
        bb3 = b_ih2[r3] + b_hh2[r3]; bb4 = b_ih2[r4] + b_hh2[r4];
    } else {
#pragma unroll
        for (int c = 0; c < 6; c++) {
            int k0 = 16 * c + 2 * q;
            WF[c][0] = pkh(W1AT(r1, k0),     W1AT(r1, k0 + 1));
            WF[c][1] = pkh(W1AT(r2, k0),     W1AT(r2, k0 + 1));
            WF[c][2] = pkh(W1AT(r1, k0 + 8), W1AT(r1, k0 + 9));
            WF[c][3] = pkh(W1AT(r2, k0 + 8), W1AT(r2, k0 + 9));
            WF[8 + c][0] = pkh(W1AT(r3, k0),     W1AT(r3, k0 + 1));
            WF[8 + c][1] = pkh(W1AT(r4, k0),     W1AT(r4, k0 + 1));
            WF[8 + c][2] = pkh(W1AT(r3, k0 + 8), W1AT(r3, k0 + 9));
            WF[8 + c][3] = pkh(W1AT(r4, k0 + 8), W1AT(r4, k0 + 9));
        }
        bb1 = b_ih1[r1] + b_hh1[r1]; bb2 = b_ih1[r2] + b_hh1[r2];
        bb3 = b_ih1[r3] + b_hh1[r3]; bb4 = b_ih1[r4] + b_hh1[r4];
    }

    if (tid < 256) { h1d[0][tid] = 0; h1d[1][tid] = 0; h2v[tid] = 0; }

    // ---- in-kernel x staging ----
    const float* xb = x + (size_t)blockIdx.x * 8 * 1024 * 32;
    const uint32_t xfb = s2u(xf);
#define STG(t_) do { int st = (t_) > 1023 ? 1023 : (t_);                          \
        const float* _s = xb + ((size_t)(L >> 2) * 1024 + st) * 32 + (L & 3) * 8; \
        uint32_t _d = xfb + (uint32_t)((((st) & 7) * 256 + (L >> 2) * 32 + (L & 3) * 8) * 4); \
        cpa16(_d, _s); cpa16(_d + 16, _s + 4);                                    \
        asm volatile("cp.async.commit_group;"); } while (0)
#define XCONV(tn) do { int m = tl & 15, bb = tl >> 4;                             \
        const float2 v = *(const float2*)&xf[(tn) & 7][bb * 32 + 2 * m];          \
        xv[(tn) & 7][m * 8 + bb] = pkh(v.x, v.y); } while (0)

    if (w == 8) {
#pragma unroll
        for (int s = 0; s < 8; s++) STG(s);
        asm volatile("cp.async.wait_group 0;");
    }
    __syncthreads();
    if (!isA && tl < 128) { XCONV(0); XCONV(1); }
    __syncthreads();

    float cx = 0.0f, cy = 0.0f;
    float pA[4] = {0,0,0,0}, pB[4] = {0,0,0,0};   // B-group carried x partials

#define ACT_STORE(ga, v0, v1, v2_, v3, rA, rB, bA, bB) do {                    \
        if (tg) { (ga)[q * GAS + (rA)] = tanh2_from((v0) + (bA), (v1) + (bA)); \
                  (ga)[q * GAS + (rB)] = tanh2_from((v2_) + (bB), (v3) + (bB)); } \
        else    { (ga)[q * GAS + (rA)] = sig2_from((v0) + (bA), (v1) + (bA));  \
                  (ga)[q * GAS + (rB)] = sig2_from((v2_) + (bB), (v3) + (bB)); } } while (0)

#define UPDATE(ga, harr) do {                                                  \
        uint32_t wi = (ga)[j * GAS + uu],        wf = (ga)[j * GAS + 64 + uu]; \
        uint32_t wg_ = (ga)[j * GAS + 128 + uu], wo = (ga)[j * GAS + 192 + uu];\
        float2 fi = __half22float2(*(__half2*)&wi);                            \
        float2 ff = __half22float2(*(__half2*)&wf);                            \
        float2 fg = __half22float2(*(__half2*)&wg_);                           \
        float2 fo = __half22float2(*(__half2*)&wo);                            \
        cx = fmaf(ff.x, cx, fi.x * fg.x);                                      \
        cy = fmaf(ff.y, cy, fi.y * fg.y);                                      \
        hx = fo.x * tanhax(cx); hy = fo.y * tanhax(cy);                        \
        __half* hp = (__half*)(harr);                                          \
        hp[(((uu >> 1) * 8 + 2 * j) << 1)     | (uu & 1)] = __float2half_rn(hx);\
        hp[(((uu >> 1) * 8 + 2 * j + 1) << 1) | (uu & 1)] = __float2half_rn(hy);\
    } while (0)

    // ---- prologue (B): g1(0) = h1(-1)[zeros] + x(0); then x(1) pre-partial ----
    if (!isA) {
        float dA[4] = {0,0,0,0}, dB[4] = {0,0,0,0};
        const uint32_t* h1c = h1d[1];
#pragma unroll
        for (int c = 0; c < 4; c++) {
            uint32_t b0w = h1c[c * 64 + bo], b1w = h1c[c * 64 + bo + 32];
            mma16(dA, WF[c], b0w, b1w); mma16(dB, WF[8 + c], b0w, b1w);
        }
#pragma unroll
        for (int c = 0; c < 2; c++) {
            uint32_t b0w = xv[0][c * 64 + bo], b1w = xv[0][c * 64 + bo + 32];
            mma16(pA, WF[4 + c], b0w, b1w); mma16(pB, WF[12 + c], b0w, b1w);
        }
        ACT_STORE(ga1h, dA[0]+pA[0], dA[1]+pA[1], dA[2]+pA[2], dA[3]+pA[3],
                  r1, r2, bb1, bb2);
        ACT_STORE(ga1h, dB[0]+pB[0], dB[1]+pB[1], dB[2]+pB[2], dB[3]+pB[3],
                  r3, r4, bb3, bb4);
        asm volatile("bar.sync 2, 256;" ::: "memory");
        float hx, hy;
        UPDATE(ga1h, h1d[0]);
        // pre-partial x(1) for round 0's gates1(1)
        pA[0]=pA[1]=pA[2]=pA[3]=0; pB[0]=pB[1]=pB[2]=pB[3]=0;
#pragma unroll
        for (int c = 0; c < 2; c++) {
            uint32_t b0w = xv[1][c * 64 + bo], b1w = xv[1][c * 64 + bo + 32];
            mma16(pA, WF[4 + c], b0w, b1w); mma16(pB, WF[12 + c], b0w, b1w);
        }
    }
    __syncthreads();

    // =================== main loop ===================
    for (int t = 0; t < T_LEN; t++) {
        if (isA) {
            // gates2(t): h1(t) + h2(t-1) — full 16 MMAs (R13 form)
            float dA[4] = {0,0,0,0}, dA2[4] = {0,0,0,0};
            float dB[4] = {0,0,0,0}, dB2[4] = {0,0,0,0};
            const uint32_t* h1c = h1d[t & 1];
#pragma unroll
            for (int c = 0; c < 4; c++) {
                uint32_t b0w = h1c[c * 64 + bo], b1w = h1c[c * 64 + bo + 32];
                mma16(dA, WF[c], b0w, b1w); mma16(dB, WF[8 + c], b0w, b1w);
            }
#pragma unroll
            for (int c = 0; c < 4; c++) {
                uint32_t b0w = h2v[c * 64 + bo], b1w = h2v[c * 64 + bo + 32];
                mma16(dA2, WF[4 + c], b0w, b1w); mma16(dB2, WF[12 + c], b0w, b1w);
            }
            ACT_STORE(ga2h, dA[0]+dA2[0], dA[1]+dA2[1], dA[2]+dA2[2], dA[3]+dA2[3],
                      r1, r2, bb1, bb2);
            ACT_STORE(ga2h, dB[0]+dB2[0], dB[1]+dB2[1], dB[2]+dB2[2], dB[3]+dB2[3],
                      r3, r4, bb3, bb4);
            asm volatile("bar.sync 1, 256;" ::: "memory");
            float hx, hy;
            UPDATE(ga2h, h2v);
            if (t == T_LEN - 1) {
                g_h2[(size_t)(blockIdx.x * 8 + 2 * j) * 64 + uu]     = hx;
                g_h2[(size_t)(blockIdx.x * 8 + 2 * j + 1) * 64 + uu] = hy;
            }
        } else {
            // gates1(t+1): post-sync only the h1(t)-dependent 8 MMAs
            float dA[4] = {0,0,0,0}, dB[4] = {0,0,0,0};
            const uint32_t* h1c = h1d[t & 1];
#pragma unroll
            for (int c = 0; c < 4; c++) {
                uint32_t b0w = h1c[c * 64 + bo], b1w = h1c[c * 64 + bo + 32];
                mma16(dA, WF[c], b0w, b1w); mma16(dB, WF[8 + c], b0w, b1w);
            }
            ACT_STORE(ga1h, dA[0]+pA[0], dA[1]+pA[1], dA[2]+pA[2], dA[3]+pA[3],
                      r1, r2, bb1, bb2);
            ACT_STORE(ga1h, dB[0]+pB[0], dB[1]+pB[1], dB[2]+pB[2], dB[3]+pB[3],
                      r3, r4, bb3, bb4);
            // XCONV off critical path: publish xv[(t+2)&7] before bar2
            if (tl < 128 && t + 2 < T_LEN) XCONV(t + 2);
            asm volatile("bar.sync 2, 256;" ::: "memory");
            float hx, hy;
            UPDATE(ga1h, h1d[(t + 1) & 1]);   // garbage at t=1023, never read
            // hoisted x(t+2) partial for round t+1 (xv visible via bar2)
            pA[0]=pA[1]=pA[2]=pA[3]=0; pB[0]=pB[1]=pB[2]=pB[3]=0;
            {
                const uint32_t* xs2 = xv[(t + 2) & 7];
#pragma unroll
                for (int c = 0; c < 2; c++) {
                    uint32_t b0w = xs2[c * 64 + bo], b1w = xs2[c * 64 + bo + 32];
                    mma16(pA, WF[4 + c], b0w, b1w); mma16(pB, WF[12 + c], b0w, b1w);
                }
            }
            if (w == 8) {
                STG(t + 8);
                asm volatile("cp.async.wait_group 4;");
            }
        }
        __syncthreads();
    }
#undef STG
#undef XCONV
#undef ACT_STORE
#undef UPDATE
}

// ---------------- head: LN(relu(h@fc1^T+b1)@fc2^T+b2) ----------------
#define HB 8
__global__ void __launch_bounds__(128)
head_kernel(const float* __restrict__ fc1_w, const float* __restrict__ fc1_b,
            const float* __restrict__ fc2_w, const float* __restrict__ fc2_b,
            const float* __restrict__ ln_g,  const float* __restrict__ ln_b,
            float* __restrict__ out) {
    extern __shared__ float hs[];
    float* w1 = hs;
    float* w2 = w1 + 128 * 65;
    float* hv = w2 + 128 * 129;
    float* y1 = hv + HB * 64;
    float* rs = y1 + 128;
    float* rq = rs + 4;
    const int tid = threadIdx.x, b0 = blockIdx.x * HB;

    for (int i = tid; i < 8192;  i += 128)
        cpa4(s2u(&w1[(i >> 6) * 65 + (i & 63)]), &fc1_w[i]);
    for (int i = tid; i < 16384; i += 128)
        cpa4(s2u(&w2[(i >> 7) * 129 + (i & 127)]), &fc2_w[i]);
    cpa16(s2u(&hv[tid * 4]), &g_h2[(size_t)b0 * 64 + tid * 4]);
    asm volatile("cp.async.commit_group;");
    asm volatile("cp.async.wait_group 0;");
    const float b1v = fc1_b[tid], b2v = fc2_b[tid];
    const float gv = ln_g[tid],   bv = ln_b[tid];
    __syncthreads();

    float a2v[HB];
#pragma unroll 1
    for (int bb = 0; bb < HB; bb++) {
        float s0 = b1v, s1 = 0.f;
#pragma unroll
        for (int k = 0; k < 64; k += 2) {
            s0 = fmaf(hv[bb * 64 + k],     w1[tid * 65 + k],     s0);
            s1 = fmaf(hv[bb * 64 + k + 1], w1[tid * 65 + k + 1], s1);
        }
        y1[tid] = fmaxf(s0 + s1, 0.0f);
        __syncthreads();
        float t0 = b2v, t1 = 0.f;
#pragma unroll
        for (int k = 0; k < 128; k += 2) {
            t0 = fmaf(y1[k],     w2[tid * 129 + k],     t0);
            t1 = fmaf(y1[k + 1], w2[tid * 129 + k + 1], t1);
        }
        a2v[bb] = t0 + t1;
        __syncthreads();
    }
#pragma unroll 1
    for (int bb = 0; bb < HB; bb++) {
        float sv = a2v[bb], sq = a2v[bb] * a2v[bb];
#pragma unroll
        for (int o = 16; o > 0; o >>= 1) {
            sv += __shfl_xor_sync(0xffffffffu, sv, o);
            sq += __shfl_xor_sync(0xffffffffu, sq, o);
        }
        if ((tid & 31) == 0) { rs[tid >> 5] = sv; rq[tid >> 5] = sq; }
        __syncthreads();
        float S = rs[0] + rs[1] + rs[2] + rs[3];
        float Q = rq[0] + rq[1] + rq[2] + rq[3];
        float mu  = S * (1.0f / 128.0f);
        float var = Q * (1.0f / 128.0f) - mu * mu;
        out[(size_t)(b0 + bb) * 128 + tid] =
            (a2v[bb] - mu) * rsqrtf(var + 1e-5f) * gv + bv;
        __syncthreads();
    }
}

extern "C" void kernel_launch(void* const* d_in, const int* in_sizes, int n_in,
                              void* d_out, int out_size) {
    const float* x     = (const float*)d_in[0];
    const float* w_ih1 = (const float*)d_in[1];
    const float* w_hh1 = (const float*)d_in[2];
    const float* b_ih1 = (const float*)d_in[3];
    const float* b_hh1 = (const float*)d_in[4];
    const float* w_ih2 = (const float*)d_in[5];
    const float* w_hh2 = (const float*)d_in[6];
    const float* b_ih2 = (const float*)d_in[7];
    const float* b_hh2 = (const float*)d_in[8];
    const float* fc1_w = (const float*)d_in[9];
    const float* fc1_b = (const float*)d_in[10];
    const float* fc2_w = (const float*)d_in[11];
    const float* fc2_b = (const float*)d_in[12];
    const float* ln_g  = (const float*)d_in[13];
    const float* ln_b  = (const float*)d_in[14];
    float* out = (float*)d_out;

    lstm_kernel<<<CTAS, TPB>>>(x, w_ih1, w_hh1, b_ih1, b_hh1,
                               w_ih2, w_hh2, b_ih2, b_hh2);

    int head_smem = (128 * 65 + 128 * 129 + HB * 64 + 128 + 8) * (int)sizeof(float);
    cudaFuncSetAttribute(head_kernel,
                         cudaFuncAttributeMaxDynamicSharedMemorySize, head_smem);
    head_kernel<<<512 / HB, 128, head_smem>>>(fc1_w, fc1_b, fc2_w, fc2_b,
                                              ln_g, ln_b, out);
}

// round 17
// speedup vs baseline: 1.1727x; 1.1727x over previous
#include <cuda_runtime.h>
#include <cuda_fp16.h>
#include <cstdint>

// R16: R13 verbatim + ONE change: ga stride 256 -> 264 (kills the 4-way
// bank conflict in ACT_STORE; UPDATE reads stay conflict-free).

#define CTAS  64
#define TPB   512
#define T_LEN 1024
#define GAS   264

static __device__ float g_h2[512 * 64];

__device__ __forceinline__ uint32_t pkh(float a, float b) {
    __half ha = __float2half_rn(a), hb = __float2half_rn(b);
    return (uint32_t)__half_as_ushort(ha) | ((uint32_t)__half_as_ushort(hb) << 16);
}
__device__ __forceinline__ float tanhax(float x) {
    float y; asm("tanh.approx.f32 %0,%1;" : "=f"(y) : "f"(x)); return y;
}
__device__ __forceinline__ uint32_t cvt2h(float hi, float lo) {
    uint32_t r; asm("cvt.rn.f16x2.f32 %0,%1,%2;" : "=r"(r) : "f"(hi), "f"(lo)); return r;
}
__device__ __forceinline__ uint32_t tanh2(uint32_t v) {
    uint32_t r; asm("tanh.approx.f16x2 %0,%1;" : "=r"(r) : "r"(v)); return r;
}
__device__ __forceinline__ uint32_t tanh2_from(float lo, float hi) {
    return tanh2(cvt2h(hi, lo));
}
__device__ __forceinline__ uint32_t sig2_from(float lo, float hi) {
    uint32_t t = tanh2(cvt2h(0.5f * hi, 0.5f * lo));
    uint32_t r;
    asm("fma.rn.f16x2 %0,%1,%2,%3;" : "=r"(r)
        : "r"(t), "r"(0x38003800u), "r"(0x38003800u));
    return r;
}
__device__ __forceinline__ void mma16(float* d, const uint32_t* a, uint32_t b0, uint32_t b1) {
    asm volatile(
        "mma.sync.aligned.m16n8k16.row.col.f32.f16.f16.f32 "
        "{%0,%1,%2,%3},{%4,%5,%6,%7},{%8,%9},{%0,%1,%2,%3};"
        : "+f"(d[0]), "+f"(d[1]), "+f"(d[2]), "+f"(d[3])
        : "r"(a[0]), "r"(a[1]), "r"(a[2]), "r"(a[3]), "r"(b0), "r"(b1));
}
__device__ __forceinline__ void cpa16(uint32_t d, const void* s) {
    asm volatile("cp.async.ca.shared.global [%0],[%1],16;" :: "r"(d), "l"(s));
}
__device__ __forceinline__ void cpa4(uint32_t d, const void* s) {
    asm volatile("cp.async.ca.shared.global [%0],[%1],4;" :: "r"(d), "l"(s));
}
__device__ __forceinline__ uint32_t s2u(const void* p) {
    uint32_t a;
    asm("{.reg .u64 t; cvta.to.shared.u64 t,%1; cvt.u32.u64 %0,t;}" : "=r"(a) : "l"(p));
    return a;
}

__global__ void __launch_bounds__(TPB, 1)
lstm_kernel(const float* __restrict__ x,
            const float* __restrict__ w_ih1, const float* __restrict__ w_hh1,
            const float* __restrict__ b_ih1, const float* __restrict__ b_hh1,
            const float* __restrict__ w_ih2, const float* __restrict__ w_hh2,
            const float* __restrict__ b_ih2, const float* __restrict__ b_hh2) {
    __shared__ uint32_t h1d[2][256];
    __shared__ uint32_t h2v[256];
    __shared__ uint32_t xv[8][128];     // fp16-pair words [m*8+b]
    __shared__ float    xf[8][256];     // fp32 staging ring [b*32+k]
    __shared__ uint32_t ga2h[4 * GAS];
    __shared__ uint32_t ga1h[4 * GAS];

    const int tid = threadIdx.x;
    const int w   = tid >> 5, L = tid & 31;
    const int wg  = w & 7;
    const int gr  = L >> 2, q = L & 3;
    const int r1  = 32 * wg + gr, r2 = r1 + 8, r3 = r1 + 16, r4 = r1 + 24;
    const int bo  = 8 * q + gr;
    const bool isA = (w < 8);
    const bool tg  = ((wg >> 1) == 2);
    const int tl  = isA ? tid : tid - 256;
    const int uu  = tl & 63, j = tl >> 6;

    uint32_t WF[16][4];
    float bb1, bb2, bb3, bb4;
#define W2AT(r, k) ((k) < 64 ? w_ih2[(r) * 64 + (k)] : w_hh2[(r) * 64 + (k) - 64])
#define W1AT(r, k) ((k) < 64 ? w_hh1[(r) * 64 + (k)] : w_ih1[(r) * 32 + (k) - 64])
    if (isA) {
#pragma unroll
        for (int c = 0; c < 8; c++) {
            int k0 = 16 * c + 2 * q;
            WF[c][0] = pkh(W2AT(r1, k0),     W2AT(r1, k0 + 1));
            WF[c][1] = pkh(W2AT(r2, k0),     W2AT(r2, k0 + 1));
            WF[c][2] = pkh(W2AT(r1, k0 + 8), W2AT(r1, k0 + 9));
            WF[c][3] = pkh(W2AT(r2, k0 + 8), W2AT(r2, k0 + 9));
            WF[8 + c][0] = pkh(W2AT(r3, k0),     W2AT(r3, k0 + 1));
            WF[8 + c][1] = pkh(W2AT(r4, k0),     W2AT(r4, k0 + 1));
            WF[8 + c][2] = pkh(W2AT(r3, k0 + 8), W2AT(r3, k0 + 9));
            WF[8 + c][3] = pkh(W2AT(r4, k0 + 8), W2AT(r4, k0 + 9));
        }
        bb1 = b_ih2[r1] + b_hh2[r1]; bb2 = b_ih2[r2] + b_hh2[r2];
        bb3 = b_ih2[r3] + b_hh2[r3]; bb4 = b_ih2[r4] + b_hh2[r4];
    } else {
#pragma unroll
        for (int c = 0; c < 6; c++) {
            int k0 = 16 * c + 2 * q;
            WF[c][0] = pkh(W1AT(r1, k0),     W1AT(r1, k0 + 1));
            WF[c][1] = pkh(W1AT(r2, k0),     W1AT(r2, k0 + 1));
            WF[c][2] = pkh(W1AT(r1, k0 + 8), W1AT(r1, k0 + 9));
            WF[c][3] = pkh(W1AT(r2, k0 + 8), W1AT(r2, k0 + 9));
            WF[8 + c][0] = pkh(W1AT(r3, k0),     W1AT(r3, k0 + 1));
            WF[8 + c][1] = pkh(W1AT(r4, k0),     W1AT(r4, k0 + 1));
            WF[8 + c][2] = pkh(W1AT(r3, k0 + 8), W1AT(r3, k0 + 9));
            WF[8 + c][3] = pkh(W1AT(r4, k0 + 8), W1AT(r4, k0 + 9));
        }
        bb1 = b_ih1[r1] + b_hh1[r1]; bb2 = b_ih1[r2] + b_hh1[r2];
        bb3 = b_ih1[r3] + b_hh1[r3]; bb4 = b_ih1[r4] + b_hh1[r4];
    }

    if (tid < 256) { h1d[0][tid] = 0; h1d[1][tid] = 0; h2v[tid] = 0; }

    // ---- in-kernel x staging ----
    const float* xb = x + (size_t)blockIdx.x * 8 * 1024 * 32;
    const uint32_t xfb = s2u(xf);
#define STG(t_) do { int st = (t_) > 1023 ? 1023 : (t_);                          \
        const float* _s = xb + ((size_t)(L >> 2) * 1024 + st) * 32 + (L & 3) * 8; \
        uint32_t _d = xfb + (uint32_t)((((st) & 7) * 256 + (L >> 2) * 32 + (L & 3) * 8) * 4); \
        cpa16(_d, _s); cpa16(_d + 16, _s + 4);                                    \
        asm volatile("cp.async.commit_group;"); } while (0)
#define XCONV(tn) do { int m = tl & 15, bb = tl >> 4;                             \
        const float2 v = *(const float2*)&xf[(tn) & 7][bb * 32 + 2 * m];          \
        xv[(tn) & 7][m * 8 + bb] = pkh(v.x, v.y); } while (0)

    if (w == 8) {
#pragma unroll
        for (int s = 0; s < 8; s++) STG(s);
        asm volatile("cp.async.wait_group 0;");
    }
    __syncthreads();
    if (!isA && tl < 128) { XCONV(0); XCONV(1); }
    __syncthreads();

    float cx = 0.0f, cy = 0.0f;

#define ACT_STORE(ga, v0, v1, v2_, v3, rA, rB, bA, bB) do {                    \
        if (tg) { (ga)[q * GAS + (rA)] = tanh2_from((v0) + (bA), (v1) + (bA)); \
                  (ga)[q * GAS + (rB)] = tanh2_from((v2_) + (bB), (v3) + (bB)); } \
        else    { (ga)[q * GAS + (rA)] = sig2_from((v0) + (bA), (v1) + (bA));  \
                  (ga)[q * GAS + (rB)] = sig2_from((v2_) + (bB), (v3) + (bB)); } } while (0)

#define UPDATE(ga, harr) do {                                                  \
        uint32_t wi = (ga)[j * GAS + uu],        wf = (ga)[j * GAS + 64 + uu]; \
        uint32_t wg_ = (ga)[j * GAS + 128 + uu], wo = (ga)[j * GAS + 192 + uu];\
        float2 fi = __half22float2(*(__half2*)&wi);                            \
        float2 ff = __half22float2(*(__half2*)&wf);                            \
        float2 fg = __half22float2(*(__half2*)&wg_);                           \
        float2 fo = __half22float2(*(__half2*)&wo);                            \
        cx = fmaf(ff.x, cx, fi.x * fg.x);                                      \
        cy = fmaf(ff.y, cy, fi.y * fg.y);                                      \
        hx = fo.x * tanhax(cx); hy = fo.y * tanhax(cy);                        \
        __half* hp = (__half*)(harr);                                          \
        hp[(((uu >> 1) * 8 + 2 * j) << 1)     | (uu & 1)] = __float2half_rn(hx);\
        hp[(((uu >> 1) * 8 + 2 * j + 1) << 1) | (uu & 1)] = __float2half_rn(hy);\
    } while (0)

    // ---- prologue: B computes g1(0) (h1(-1)=0 via zeroed h1d[1]) ----
    if (!isA) {
        float dA[4] = {0,0,0,0}, dA2[4] = {0,0,0,0};
        float dB[4] = {0,0,0,0}, dB2[4] = {0,0,0,0};
        const uint32_t* h1c = h1d[1];
#pragma unroll
        for (int c = 0; c < 4; c++) {
            uint32_t b0w = h1c[c * 64 + bo], b1w = h1c[c * 64 + bo + 32];
            mma16(dA, WF[c], b0w, b1w); mma16(dB, WF[8 + c], b0w, b1w);
        }
#pragma unroll
        for (int c = 0; c < 2; c++) {
            uint32_t b0w = xv[0][c * 64 + bo], b1w = xv[0][c * 64 + bo + 32];
            mma16(dA2, WF[4 + c], b0w, b1w); mma16(dB2, WF[12 + c], b0w, b1w);
        }
        ACT_STORE(ga1h, dA[0]+dA2[0], dA[1]+dA2[1], dA[2]+dA2[2], dA[3]+dA2[3],
                  r1, r2, bb1, bb2);
        ACT_STORE(ga1h, dB[0]+dB2[0], dB[1]+dB2[1], dB[2]+dB2[2], dB[3]+dB2[3],
                  r3, r4, bb3, bb4);
        asm volatile("bar.sync 2, 256;" ::: "memory");
        float hx, hy;
        UPDATE(ga1h, h1d[0]);
    }
    __syncthreads();

    // =================== main loop ===================
    for (int t = 0; t < T_LEN; t++) {
        if (isA) {
            // gates2(t): h1(t) + h2(t-1), split chains
            float dA[4] = {0,0,0,0}, dA2[4] = {0,0,0,0};
            float dB[4] = {0,0,0,0}, dB2[4] = {0,0,0,0};
            const uint32_t* h1c = h1d[t & 1];
#pragma unroll
            for (int c = 0; c < 4; c++) {
                uint32_t b0w = h1c[c * 64 + bo], b1w = h1c[c * 64 + bo + 32];
                mma16(dA, WF[c], b0w, b1w); mma16(dB, WF[8 + c], b0w, b1w);
            }
#pragma unroll
            for (int c = 0; c < 4; c++) {
                uint32_t b0w = h2v[c * 64 + bo], b1w = h2v[c * 64 + bo + 32];
                mma16(dA2, WF[4 + c], b0w, b1w); mma16(dB2, WF[12 + c], b0w, b1w);
            }
            ACT_STORE(ga2h, dA[0]+dA2[0], dA[1]+dA2[1], dA[2]+dA2[2], dA[3]+dA2[3],
                      r1, r2, bb1, bb2);
            ACT_STORE(ga2h, dB[0]+dB2[0], dB[1]+dB2[1], dB[2]+dB2[2], dB[3]+dB2[3],
                      r3, r4, bb3, bb4);
            asm volatile("bar.sync 1, 256;" ::: "memory");
            float hx, hy;
            UPDATE(ga2h, h2v);
            if (t == T_LEN - 1) {
                g_h2[(size_t)(blockIdx.x * 8 + 2 * j) * 64 + uu]     = hx;
                g_h2[(size_t)(blockIdx.x * 8 + 2 * j + 1) * 64 + uu] = hy;
            }
        } else {
            if (w == 8) STG(t + 8);
            if (tl < 128 && t + 2 < T_LEN) XCONV(t + 2);
            // gates1(t+1): h1(t) + x(t+1), split chains
            float dA[4] = {0,0,0,0}, dA2[4] = {0,0,0,0};
            float dB[4] = {0,0,0,0}, dB2[4] = {0,0,0,0};
            const uint32_t* h1c = h1d[t & 1];
            const uint32_t* xs  = xv[(t + 1) & 7];
#pragma unroll
            for (int c = 0; c < 4; c++) {
                uint32_t b0w = h1c[c * 64 + bo], b1w = h1c[c * 64 + bo + 32];
                mma16(dA, WF[c], b0w, b1w); mma16(dB, WF[8 + c], b0w, b1w);
            }
#pragma unroll
            for (int c = 0; c < 2; c++) {
                uint32_t b0w = xs[c * 64 + bo], b1w = xs[c * 64 + bo + 32];
                mma16(dA2, WF[4 + c], b0w, b1w); mma16(dB2, WF[12 + c], b0w, b1w);
            }
            ACT_STORE(ga1h, dA[0]+dA2[0], dA[1]+dA2[1], dA[2]+dA2[2], dA[3]+dA2[3],
                      r1, r2, bb1, bb2);
            ACT_STORE(ga1h, dB[0]+dB2[0], dB[1]+dB2[1], dB[2]+dB2[2], dB[3]+dB2[3],
                      r3, r4, bb3, bb4);
            asm volatile("bar.sync 2, 256;" ::: "memory");
            float hx, hy;
            UPDATE(ga1h, h1d[(t + 1) & 1]);   // garbage at t=1023, never read
            if (w == 8) asm volatile("cp.async.wait_group 4;");
        }
        __syncthreads();
    }
#undef STG
#undef XCONV
#undef ACT_STORE
#undef UPDATE
}

// ---------------- head: LN(relu(h@fc1^T+b1)@fc2^T+b2) ----------------
#define HB 8
__global__ void __launch_bounds__(128)
head_kernel(const float* __restrict__ fc1_w, const float* __restrict__ fc1_b,
            const float* __restrict__ fc2_w, const float* __restrict__ fc2_b,
            const float* __restrict__ ln_g,  const float* __restrict__ ln_b,
            float* __restrict__ out) {
    extern __shared__ float hs[];
    float* w1 = hs;
    float* w2 = w1 + 128 * 65;
    float* hv = w2 + 128 * 129;
    float* y1 = hv + HB * 64;
    float* rs = y1 + 128;
    float* rq = rs + 4;
    const int tid = threadIdx.x, b0 = blockIdx.x * HB;

    for (int i = tid; i < 8192;  i += 128)
        cpa4(s2u(&w1[(i >> 6) * 65 + (i & 63)]), &fc1_w[i]);
    for (int i = tid; i < 16384; i += 128)
        cpa4(s2u(&w2[(i >> 7) * 129 + (i & 127)]), &fc2_w[i]);
    cpa16(s2u(&hv[tid * 4]), &g_h2[(size_t)b0 * 64 + tid * 4]);
    asm volatile("cp.async.commit_group;");
    asm volatile("cp.async.wait_group 0;");
    const float b1v = fc1_b[tid], b2v = fc2_b[tid];
    const float gv = ln_g[tid],   bv = ln_b[tid];
    __syncthreads();

    float a2v[HB];
#pragma unroll 1
    for (int bb = 0; bb < HB; bb++) {
        float s0 = b1v, s1 = 0.f;
#pragma unroll
        for (int k = 0; k < 64; k += 2) {
            s0 = fmaf(hv[bb * 64 + k],     w1[tid * 65 + k],     s0);
            s1 = fmaf(hv[bb * 64 + k + 1], w1[tid * 65 + k + 1], s1);
        }
        y1[tid] = fmaxf(s0 + s1, 0.0f);
        __syncthreads();
        float t0 = b2v, t1 = 0.f;
#pragma unroll
        for (int k = 0; k < 128; k += 2) {
            t0 = fmaf(y1[k],     w2[tid * 129 + k],     t0);
            t1 = fmaf(y1[k + 1], w2[tid * 129 + k + 1], t1);
        }
        a2v[bb] = t0 + t1;
        __syncthreads();
    }
#pragma unroll 1
    for (int bb = 0; bb < HB; bb++) {
        float sv = a2v[bb], sq = a2v[bb] * a2v[bb];
#pragma unroll
        for (int o = 16; o > 0; o >>= 1) {
            sv += __shfl_xor_sync(0xffffffffu, sv, o);
            sq += __shfl_xor_sync(0xffffffffu, sq, o);
        }
        if ((tid & 31) == 0) { rs[tid >> 5] = sv; rq[tid >> 5] = sq; }
        __syncthreads();
        float S = rs[0] + rs[1] + rs[2] + rs[3];
        float Q = rq[0] + rq[1] + rq[2] + rq[3];
        float mu  = S * (1.0f / 128.0f);
        float var = Q * (1.0f / 128.0f) - mu * mu;
        out[(size_t)(b0 + bb) * 128 + tid] =
            (a2v[bb] - mu) * rsqrtf(var + 1e-5f) * gv + bv;
        __syncthreads();
    }
}

extern "C" void kernel_launch(void* const* d_in, const int* in_sizes, int n_in,
                              void* d_out, int out_size) {
    const float* x     = (const float*)d_in[0];
    const float* w_ih1 = (const float*)d_in[1];
    const float* w_hh1 = (const float*)d_in[2];
    const float* b_ih1 = (const float*)d_in[3];
    const float* b_hh1 = (const float*)d_in[4];
    const float* w_ih2 = (const float*)d_in[5];
    const float* w_hh2 = (const float*)d_in[6];
    const float* b_ih2 = (const float*)d_in[7];
    const float* b_hh2 = (const float*)d_in[8];
    const float* fc1_w = (const float*)d_in[9];
    const float* fc1_b = (const float*)d_in[10];
    const float* fc2_w = (const float*)d_in[11];
    const float* fc2_b = (const float*)d_in[12];
    const float* ln_g  = (const float*)d_in[13];
    const float* ln_b  = (const float*)d_in[14];
    float* out = (float*)d_out;

    lstm_kernel<<<CTAS, TPB>>>(x, w_ih1, w_hh1, b_ih1, b_hh1,
                               w_ih2, w_hh2, b_ih2, b_hh2);

    int head_smem = (128 * 65 + 128 * 129 + HB * 64 + 128 + 8) * (int)sizeof(float);
    cudaFuncSetAttribute(head_kernel,
                         cudaFuncAttributeMaxDynamicSharedMemorySize, head_smem);
    head_kernel<<<512 / HB, 128, head_smem>>>(fc1_w, fc1_b, fc2_w, fc2_b,
                                              ln_g, ln_b, out);
}